// round 1
// baseline (speedup 1.0000x reference)
#include <cuda_runtime.h>

#define NN 50000
#define EE 800000
#define FIN 128
#define HH 4
#define CC 73
#define HCV 292
#define BN_EPS 1e-5f

// ---------------- scratch (static device globals; no allocs) ----------------
__device__ float g_xl[(size_t)NN * HCV];   // 58.4 MB
__device__ float g_xr[(size_t)NN * HCV];   // 58.4 MB
__device__ float g_h [(size_t)NN * HCV];   // 58.4 MB  (layer output / next input)
__device__ float g_s [(size_t)EE * HH];    // 12.8 MB  (scores, then exp())
__device__ float g_m  [NN * HH];
__device__ float g_den[NN * HH];
__device__ float g_stats[2 * HCV];
__device__ int   g_src[EE];
__device__ int   g_dst[EE];
__device__ int   g_is64;

// ---------------- edge index dtype detect + convert ----------------
__global__ void detect_dtype(const unsigned int* ei) {
    // If the buffer is int64, every odd 32-bit word (high word) is 0
    // (values are in [0, 50000)). If int32, odd words are random node ids.
    unsigned acc = 0;
    for (int i = threadIdx.x; i < 2048; i += 32) acc |= ei[2 * i + 1];
    #pragma unroll
    for (int o = 16; o; o >>= 1) acc |= __shfl_xor_sync(0xffffffffu, acc, o);
    if (threadIdx.x == 0) g_is64 = (acc == 0u) ? 1 : 0;
}

__global__ void convert_edges(const void* ei) {
    int i = blockIdx.x * blockDim.x + threadIdx.x;
    if (i >= EE) return;
    if (g_is64) {
        const long long* p = (const long long*)ei;
        g_src[i] = (int)p[i];
        g_dst[i] = (int)p[EE + i];
    } else {
        const int* p = (const int*)ei;
        g_src[i] = p[i];
        g_dst[i] = p[EE + i];
    }
}

// ---------------- GEMM: C[n, j] = sum_k A[n,k] * W[j,k] + bias[j] ----------------
// A: [nrows, K] row-major, W: [HCV, K] row-major, C: [nrows, HCV]
__global__ void gemm_bias(const float* __restrict__ A, const float* __restrict__ W,
                          const float* __restrict__ bias, float* __restrict__ C,
                          int nrows, int K) {
    const int BM = 128, BN = 64, BK = 16;
    __shared__ __align__(16) float As[BK][BM + 4];
    __shared__ __align__(16) float Ws[BK][BN + 4];
    int tid = threadIdx.x;               // 256 threads
    int tx = tid & 15, ty = tid >> 4;    // 16 x 16
    int row0 = blockIdx.x * BM, col0 = blockIdx.y * BN;
    float acc[8][4];
    #pragma unroll
    for (int i = 0; i < 8; i++)
        #pragma unroll
        for (int j = 0; j < 4; j++) acc[i][j] = 0.f;

    for (int k0 = 0; k0 < K; k0 += BK) {
        #pragma unroll
        for (int i = tid; i < BM * BK; i += 256) {
            int r = i >> 4, c = i & 15;
            int gr = row0 + r, gc = k0 + c;
            As[c][r] = (gr < nrows && gc < K) ? A[(size_t)gr * K + gc] : 0.f;
        }
        #pragma unroll
        for (int i = tid; i < BN * BK; i += 256) {
            int r = i >> 4, c = i & 15;
            int gr = col0 + r, gc = k0 + c;
            Ws[c][r] = (gr < HCV && gc < K) ? W[(size_t)gr * K + gc] : 0.f;
        }
        __syncthreads();
        #pragma unroll
        for (int kk = 0; kk < BK; kk++) {
            float4 a0 = *reinterpret_cast<const float4*>(&As[kk][ty * 8]);
            float4 a1 = *reinterpret_cast<const float4*>(&As[kk][ty * 8 + 4]);
            float4 b0 = *reinterpret_cast<const float4*>(&Ws[kk][tx * 4]);
            float a[8] = {a0.x, a0.y, a0.z, a0.w, a1.x, a1.y, a1.z, a1.w};
            float b[4] = {b0.x, b0.y, b0.z, b0.w};
            #pragma unroll
            for (int i = 0; i < 8; i++)
                #pragma unroll
                for (int j = 0; j < 4; j++) acc[i][j] += a[i] * b[j];
        }
        __syncthreads();
    }
    #pragma unroll
    for (int i = 0; i < 8; i++) {
        int gr = row0 + ty * 8 + i;
        if (gr >= nrows) continue;
        #pragma unroll
        for (int j = 0; j < 4; j++) {
            int gc = col0 + tx * 4 + j;
            if (gc < HCV) C[(size_t)gr * HCV + gc] = acc[i][j] + bias[gc];
        }
    }
}

// ---------------- per-layer init ----------------
__global__ void init_mden() {
    int i = blockIdx.x * blockDim.x + threadIdx.x;
    if (i < NN * HH) {
        g_m[i] = __int_as_float(0xff800000);   // -inf
        g_den[i] = 0.f;
    }
}

__global__ void set_bias(const float* __restrict__ b) {
    int n = blockIdx.x, t = threadIdx.x;
    if (t < HCV) g_h[(size_t)n * HCV + t] = b[t];
}

// ---------------- edge kernels ----------------
__device__ __forceinline__ void atomicMaxFloat(float* addr, float val) {
    if (val >= 0.f) atomicMax((int*)addr, __float_as_int(val));
    else            atomicMin((unsigned int*)addr, (unsigned int)__float_as_int(val));
}

// warp per (edge, head): score + atomic max into g_m
__global__ void edge_score(const float* __restrict__ att) {
    int wg = (blockIdx.x * blockDim.x + threadIdx.x) >> 5;
    int lane = threadIdx.x & 31;
    if (wg >= EE * HH) return;
    int e = wg >> 2, h = wg & 3;
    int s = g_src[e], d = g_dst[e];
    const float* xl = g_xl + (size_t)s * HCV + h * CC;
    const float* xr = g_xr + (size_t)d * HCV + h * CC;
    const float* a  = att + h * CC;
    float acc = 0.f;
    for (int c = lane; c < CC; c += 32) {
        float f = xl[c] + xr[c];
        f = (f >= 0.f) ? f : 0.2f * f;
        acc += f * __ldg(&a[c]);
    }
    #pragma unroll
    for (int o = 16; o; o >>= 1) acc += __shfl_xor_sync(0xffffffffu, acc, o);
    if (lane == 0) {
        g_s[(size_t)e * HH + h] = acc;
        atomicMaxFloat(&g_m[d * HH + h], acc);
    }
}

// thread per (edge, head): exp(s - m[dst]) and atomic denominator
__global__ void edge_exp() {
    int t = blockIdx.x * blockDim.x + threadIdx.x;
    if (t >= EE * HH) return;
    int e = t >> 2, h = t & 3;
    int d = g_dst[e];
    float ex = expf(g_s[t] - g_m[d * HH + h]);
    g_s[t] = ex;
    atomicAdd(&g_den[d * HH + h], ex);
}

// warp per (edge, head): out[dst] += alpha * xl[src]
__global__ void edge_aggr() {
    int wg = (blockIdx.x * blockDim.x + threadIdx.x) >> 5;
    int lane = threadIdx.x & 31;
    if (wg >= EE * HH) return;
    int e = wg >> 2, h = wg & 3;
    int s = g_src[e], d = g_dst[e];
    float alpha = g_s[(size_t)e * HH + h] / (g_den[d * HH + h] + 1e-16f);
    const float* xl = g_xl + (size_t)s * HCV + h * CC;
    float* outp = g_h + (size_t)d * HCV + h * CC;
    for (int c = lane; c < CC; c += 32)
        atomicAdd(&outp[c], alpha * xl[c]);
}

// ---------------- batchnorm ----------------
__global__ void zero_stats() {
    int t = threadIdx.x;
    if (t < 2 * HCV) g_stats[t] = 0.f;
}

__global__ void bn_stats() {
    int t = threadIdx.x;
    if (t >= HCV) return;
    float s = 0.f, sq = 0.f;
    for (int n = blockIdx.x; n < NN; n += gridDim.x) {
        float v = g_h[(size_t)n * HCV + t];
        s += v; sq += v * v;
    }
    atomicAdd(&g_stats[t], s);
    atomicAdd(&g_stats[HCV + t], sq);
}

__global__ void bn_apply(const float* __restrict__ gamma, const float* __restrict__ beta) {
    int t = threadIdx.x;
    if (t >= HCV) return;
    float mu = g_stats[t] * (1.f / NN);
    float var = g_stats[HCV + t] * (1.f / NN) - mu * mu;
    float sc = rsqrtf(var + BN_EPS) * gamma[t];
    float bt = beta[t];
    for (int n = blockIdx.x; n < NN; n += gridDim.x) {
        size_t idx = (size_t)n * HCV + t;
        float y = (g_h[idx] - mu) * sc + bt;
        g_h[idx] = (y >= 0.f) ? y : 0.01f * y;
    }
}

// ---------------- classifier ----------------
__global__ void classifier(const float* __restrict__ Wc, const float* __restrict__ bc,
                           float* __restrict__ out) {
    int w = (blockIdx.x * blockDim.x + threadIdx.x) >> 5;
    int lane = threadIdx.x & 31;
    if (w >= NN) return;
    const float* hrow = g_h + (size_t)w * HCV;
    float c0 = 0.f, c1 = 0.f;
    for (int j = lane; j < HCV; j += 32) {
        float v = hrow[j];
        c0 += v * __ldg(&Wc[j]);
        c1 += v * __ldg(&Wc[HCV + j]);
    }
    #pragma unroll
    for (int o = 16; o; o >>= 1) {
        c0 += __shfl_xor_sync(0xffffffffu, c0, o);
        c1 += __shfl_xor_sync(0xffffffffu, c1, o);
    }
    if (lane == 0) {
        out[2 * w]     = c0 + bc[0];
        out[2 * w + 1] = c1 + bc[1];
    }
}

// ---------------- host orchestration ----------------
extern "C" void kernel_launch(void* const* d_in, const int* in_sizes, int n_in,
                              void* d_out, int out_size) {
    const float* x    = (const float*)d_in[0];
    const void*  ei   = d_in[1];
    const float* Wl1  = (const float*)d_in[2];
    const float* bl1  = (const float*)d_in[3];
    const float* Wr1  = (const float*)d_in[4];
    const float* br1  = (const float*)d_in[5];
    const float* att1 = (const float*)d_in[6];
    const float* b1   = (const float*)d_in[7];
    const float* Wl2  = (const float*)d_in[8];
    const float* bl2  = (const float*)d_in[9];
    const float* Wr2  = (const float*)d_in[10];
    const float* br2  = (const float*)d_in[11];
    const float* att2 = (const float*)d_in[12];
    const float* b2   = (const float*)d_in[13];
    const float* gamma = (const float*)d_in[14];
    const float* beta  = (const float*)d_in[15];
    const float* Wc   = (const float*)d_in[16];
    const float* bc   = (const float*)d_in[17];
    float* out = (float*)d_out;

    float *xl, *xr, *h;
    cudaGetSymbolAddress((void**)&xl, g_xl);
    cudaGetSymbolAddress((void**)&xr, g_xr);
    cudaGetSymbolAddress((void**)&h,  g_h);

    detect_dtype<<<1, 32>>>((const unsigned int*)ei);
    convert_edges<<<(EE + 255) / 256, 256>>>(ei);

    dim3 ggrid((NN + 127) / 128, (HCV + 63) / 64);
    const int warpBlocks = (EE * HH) / 8;           // 8 warps per 256-thread block

    // ---- layer 1 ----
    gemm_bias<<<ggrid, 256>>>(x, Wl1, bl1, xl, NN, FIN);
    gemm_bias<<<ggrid, 256>>>(x, Wr1, br1, xr, NN, FIN);
    init_mden<<<(NN * HH + 255) / 256, 256>>>();
    set_bias<<<NN, 320>>>(b1);
    edge_score<<<warpBlocks, 256>>>(att1);
    edge_exp<<<(EE * HH + 255) / 256, 256>>>();
    edge_aggr<<<warpBlocks, 256>>>();
    zero_stats<<<1, 640>>>();
    bn_stats<<<512, 320>>>();
    bn_apply<<<1024, 320>>>(gamma, beta);

    // ---- layer 2 ----
    gemm_bias<<<ggrid, 256>>>(h, Wl2, bl2, xl, NN, HCV);
    gemm_bias<<<ggrid, 256>>>(h, Wr2, br2, xr, NN, HCV);
    init_mden<<<(NN * HH + 255) / 256, 256>>>();
    set_bias<<<NN, 320>>>(b2);
    edge_score<<<warpBlocks, 256>>>(att2);
    edge_exp<<<(EE * HH + 255) / 256, 256>>>();
    edge_aggr<<<warpBlocks, 256>>>();
    zero_stats<<<1, 640>>>();
    bn_stats<<<512, 320>>>();
    bn_apply<<<1024, 320>>>(gamma, beta);

    classifier<<<(NN * 32 + 255) / 256, 256>>>(Wc, bc, out);
}

// round 2
// speedup vs baseline: 1.6059x; 1.6059x over previous
#include <cuda_runtime.h>

#define NN 50000
#define EE 800000
#define FIN 128
#define HH 4
#define CC 73
#define HCV 292
#define BN_EPS 1e-5f
#define NEG_INF __int_as_float(0xff800000)

// ---------------- scratch (static device globals) ----------------
__device__ float g_xl[(size_t)NN * HCV];
__device__ float g_xr[(size_t)NN * HCV];
__device__ float g_h [(size_t)NN * HCV];
__device__ float g_s [(size_t)EE * HH];     // scores / exp, CSR-ordered
__device__ float g_stats[2 * HCV];
__device__ int   g_src[EE];
__device__ int   g_dst[EE];
__device__ int   g_cnt[NN];
__device__ int   g_off[NN];
__device__ int   g_fill[NN];
__device__ int   g_csrc[EE];                // CSR: src node per slot
__device__ int   g_is64;

// ---------------- edge index dtype detect + convert ----------------
__global__ void detect_dtype(const unsigned int* ei) {
    unsigned acc = 0;
    for (int i = threadIdx.x; i < 2048; i += 32) acc |= ei[2 * i + 1];
    #pragma unroll
    for (int o = 16; o; o >>= 1) acc |= __shfl_xor_sync(0xffffffffu, acc, o);
    if (threadIdx.x == 0) g_is64 = (acc == 0u) ? 1 : 0;
}

__global__ void convert_edges(const void* ei) {
    int i = blockIdx.x * blockDim.x + threadIdx.x;
    if (i >= EE) return;
    if (g_is64) {
        const long long* p = (const long long*)ei;
        g_src[i] = (int)p[i];
        g_dst[i] = (int)p[EE + i];
    } else {
        const int* p = (const int*)ei;
        g_src[i] = p[i];
        g_dst[i] = p[EE + i];
    }
}

// ---------------- CSR build ----------------
__global__ void zero_cnt() {
    int i = blockIdx.x * blockDim.x + threadIdx.x;
    if (i < NN) { g_cnt[i] = 0; g_fill[i] = 0; }
}
__global__ void hist_dst() {
    int e = blockIdx.x * blockDim.x + threadIdx.x;
    if (e < EE) atomicAdd(&g_cnt[g_dst[e]], 1);
}
__global__ void scan_off() {     // 1 block, 1024 threads
    __shared__ int part[1024];
    int t = threadIdx.x;
    const int PER = (NN + 1023) / 1024;
    int base = t * PER;
    int sum = 0;
    for (int i = 0; i < PER; i++) { int j = base + i; if (j < NN) sum += g_cnt[j]; }
    part[t] = sum;
    __syncthreads();
    for (int o = 1; o < 1024; o <<= 1) {
        int v = 0;
        if (t >= o) v = part[t - o];
        __syncthreads();
        if (t >= o) part[t] += v;
        __syncthreads();
    }
    int run = (t == 0) ? 0 : part[t - 1];
    for (int i = 0; i < PER; i++) {
        int j = base + i;
        if (j < NN) { g_off[j] = run; run += g_cnt[j]; }
    }
}
__global__ void scatter_csr() {
    int e = blockIdx.x * blockDim.x + threadIdx.x;
    if (e >= EE) return;
    int d = g_dst[e];
    int p = g_off[d] + atomicAdd(&g_fill[d], 1);
    g_csrc[p] = g_src[e];
}

// ---------------- GEMM: C = A @ W^T + bias,  A:[nrows,K], W:[HCV,K] ----------------
__global__ void gemm_bias(const float* __restrict__ A, const float* __restrict__ W,
                          const float* __restrict__ bias, float* __restrict__ C,
                          int nrows, int K) {
    const int BM = 128, BN = 128, BK = 16;
    __shared__ __align__(16) float As[BK][BM + 4];
    __shared__ __align__(16) float Ws[BK][BN + 4];
    int tid = threadIdx.x;               // 256 threads
    int tx = tid & 15, ty = tid >> 4;    // 16 x 16, each does 8x8
    int row0 = blockIdx.x * BM, col0 = blockIdx.y * BN;
    float acc[8][8];
    #pragma unroll
    for (int i = 0; i < 8; i++)
        #pragma unroll
        for (int j = 0; j < 8; j++) acc[i][j] = 0.f;

    for (int k0 = 0; k0 < K; k0 += BK) {
        #pragma unroll
        for (int i = tid; i < BM * BK; i += 256) {
            int r = i >> 4, c = i & 15;
            int gr = row0 + r, gc = k0 + c;
            As[c][r] = (gr < nrows && gc < K) ? A[(size_t)gr * K + gc] : 0.f;
        }
        #pragma unroll
        for (int i = tid; i < BN * BK; i += 256) {
            int r = i >> 4, c = i & 15;
            int gr = col0 + r, gc = k0 + c;
            Ws[c][r] = (gr < HCV && gc < K) ? W[(size_t)gr * K + gc] : 0.f;
        }
        __syncthreads();
        #pragma unroll
        for (int kk = 0; kk < BK; kk++) {
            float4 a0 = *reinterpret_cast<const float4*>(&As[kk][ty * 8]);
            float4 a1 = *reinterpret_cast<const float4*>(&As[kk][ty * 8 + 4]);
            float4 b0 = *reinterpret_cast<const float4*>(&Ws[kk][tx * 8]);
            float4 b1 = *reinterpret_cast<const float4*>(&Ws[kk][tx * 8 + 4]);
            float a[8] = {a0.x, a0.y, a0.z, a0.w, a1.x, a1.y, a1.z, a1.w};
            float b[8] = {b0.x, b0.y, b0.z, b0.w, b1.x, b1.y, b1.z, b1.w};
            #pragma unroll
            for (int i = 0; i < 8; i++)
                #pragma unroll
                for (int j = 0; j < 8; j++) acc[i][j] += a[i] * b[j];
        }
        __syncthreads();
    }
    #pragma unroll
    for (int i = 0; i < 8; i++) {
        int gr = row0 + ty * 8 + i;
        if (gr >= nrows) continue;
        #pragma unroll
        for (int j = 0; j < 8; j++) {
            int gc = col0 + tx * 8 + j;
            if (gc < HCV) C[(size_t)gr * HCV + gc] = acc[i][j] + bias[gc];
        }
    }
}

// ---------------- fused GATv2 node kernel: warp per node, all heads ----------------
__global__ void gat_node(const float* __restrict__ att, const float* __restrict__ b) {
    int warp = (blockIdx.x * blockDim.x + threadIdx.x) >> 5;
    int lane = threadIdx.x & 31;
    if (warp >= NN) return;
    int n = warp;

    float xrr[10], attv[10];
    int hd[10];
    #pragma unroll
    for (int k = 0; k < 10; k++) {
        int c = lane + 32 * k;
        bool ok = c < HCV;
        xrr[k]  = ok ? g_xr[(size_t)n * HCV + c] : 0.f;
        attv[k] = ok ? __ldg(&att[c]) : 0.f;
        hd[k]   = ok ? (c / CC) : 0;
    }
    int beg = g_off[n], cnt = g_cnt[n];

    // ---- pass A: scores + per-head max ----
    float mx0 = NEG_INF, mx1 = NEG_INF, mx2 = NEG_INF, mx3 = NEG_INF;
    for (int i = 0; i < cnt; i++) {
        const float* xl = g_xl + (size_t)g_csrc[beg + i] * HCV;
        float a0 = 0.f, a1 = 0.f, a2 = 0.f, a3 = 0.f;
        #pragma unroll
        for (int k = 0; k < 10; k++) {
            int c = lane + 32 * k;
            float v = (c < HCV) ? xl[c] : 0.f;
            float f = v + xrr[k];
            f = (f >= 0.f) ? f : 0.2f * f;
            float p = f * attv[k];
            if      (hd[k] == 0) a0 += p;
            else if (hd[k] == 1) a1 += p;
            else if (hd[k] == 2) a2 += p;
            else                 a3 += p;
        }
        #pragma unroll
        for (int o = 16; o; o >>= 1) {
            a0 += __shfl_xor_sync(0xffffffffu, a0, o);
            a1 += __shfl_xor_sync(0xffffffffu, a1, o);
            a2 += __shfl_xor_sync(0xffffffffu, a2, o);
            a3 += __shfl_xor_sync(0xffffffffu, a3, o);
        }
        mx0 = fmaxf(mx0, a0); mx1 = fmaxf(mx1, a1);
        mx2 = fmaxf(mx2, a2); mx3 = fmaxf(mx3, a3);
        if (lane < 4) {
            float s = (lane == 0) ? a0 : (lane == 1) ? a1 : (lane == 2) ? a2 : a3;
            g_s[(size_t)(beg + i) * 4 + lane] = s;
        }
    }

    // ---- pass B: exp + denominators ----
    float d0 = 0.f, d1 = 0.f, d2 = 0.f, d3 = 0.f;
    for (int j = lane; j < cnt * 4; j += 32) {
        int h = j & 3;
        float mh = (h == 0) ? mx0 : (h == 1) ? mx1 : (h == 2) ? mx2 : mx3;
        float ex = __expf(g_s[(size_t)beg * 4 + j] - mh);
        g_s[(size_t)beg * 4 + j] = ex;
        if      (h == 0) d0 += ex;
        else if (h == 1) d1 += ex;
        else if (h == 2) d2 += ex;
        else             d3 += ex;
    }
    #pragma unroll
    for (int o = 16; o; o >>= 1) {
        d0 += __shfl_xor_sync(0xffffffffu, d0, o);
        d1 += __shfl_xor_sync(0xffffffffu, d1, o);
        d2 += __shfl_xor_sync(0xffffffffu, d2, o);
        d3 += __shfl_xor_sync(0xffffffffu, d3, o);
    }
    float i0 = 1.f / (d0 + 1e-16f), i1 = 1.f / (d1 + 1e-16f);
    float i2 = 1.f / (d2 + 1e-16f), i3 = 1.f / (d3 + 1e-16f);

    // ---- pass C: weighted aggregation in registers ----
    float out[10];
    #pragma unroll
    for (int k = 0; k < 10; k++) out[k] = 0.f;
    for (int i = 0; i < cnt; i++) {
        float my = 0.f;
        if (lane < 4) {
            float inv = (lane == 0) ? i0 : (lane == 1) ? i1 : (lane == 2) ? i2 : i3;
            my = g_s[(size_t)(beg + i) * 4 + lane] * inv;
        }
        float al0 = __shfl_sync(0xffffffffu, my, 0);
        float al1 = __shfl_sync(0xffffffffu, my, 1);
        float al2 = __shfl_sync(0xffffffffu, my, 2);
        float al3 = __shfl_sync(0xffffffffu, my, 3);
        const float* xl = g_xl + (size_t)g_csrc[beg + i] * HCV;
        #pragma unroll
        for (int k = 0; k < 10; k++) {
            int c = lane + 32 * k;
            float v = (c < HCV) ? xl[c] : 0.f;
            float al = (hd[k] == 0) ? al0 : (hd[k] == 1) ? al1 : (hd[k] == 2) ? al2 : al3;
            out[k] += al * v;
        }
    }
    #pragma unroll
    for (int k = 0; k < 10; k++) {
        int c = lane + 32 * k;
        if (c < HCV) g_h[(size_t)n * HCV + c] = out[k] + __ldg(&b[c]);
    }
}

// ---------------- batchnorm ----------------
__global__ void zero_stats() {
    int t = threadIdx.x;
    if (t < 2 * HCV) g_stats[t] = 0.f;
}
__global__ void bn_stats() {
    int t = threadIdx.x;
    if (t >= HCV) return;
    float s = 0.f, sq = 0.f;
    for (int n = blockIdx.x; n < NN; n += gridDim.x) {
        float v = g_h[(size_t)n * HCV + t];
        s += v; sq += v * v;
    }
    atomicAdd(&g_stats[t], s);
    atomicAdd(&g_stats[HCV + t], sq);
}
__global__ void bn_apply(const float* __restrict__ gamma, const float* __restrict__ beta) {
    int t = threadIdx.x;
    if (t >= HCV) return;
    float mu = g_stats[t] * (1.f / NN);
    float var = g_stats[HCV + t] * (1.f / NN) - mu * mu;
    float sc = rsqrtf(var + BN_EPS) * gamma[t];
    float bt = beta[t];
    for (int n = blockIdx.x; n < NN; n += gridDim.x) {
        size_t idx = (size_t)n * HCV + t;
        float y = (g_h[idx] - mu) * sc + bt;
        g_h[idx] = (y >= 0.f) ? y : 0.01f * y;
    }
}

// ---------------- classifier ----------------
__global__ void classifier(const float* __restrict__ Wc, const float* __restrict__ bc,
                           float* __restrict__ out) {
    int w = (blockIdx.x * blockDim.x + threadIdx.x) >> 5;
    int lane = threadIdx.x & 31;
    if (w >= NN) return;
    const float* hrow = g_h + (size_t)w * HCV;
    float c0 = 0.f, c1 = 0.f;
    for (int j = lane; j < HCV; j += 32) {
        float v = hrow[j];
        c0 += v * __ldg(&Wc[j]);
        c1 += v * __ldg(&Wc[HCV + j]);
    }
    #pragma unroll
    for (int o = 16; o; o >>= 1) {
        c0 += __shfl_xor_sync(0xffffffffu, c0, o);
        c1 += __shfl_xor_sync(0xffffffffu, c1, o);
    }
    if (lane == 0) {
        out[2 * w]     = c0 + bc[0];
        out[2 * w + 1] = c1 + bc[1];
    }
}

// ---------------- host orchestration ----------------
extern "C" void kernel_launch(void* const* d_in, const int* in_sizes, int n_in,
                              void* d_out, int out_size) {
    const float* x    = (const float*)d_in[0];
    const void*  ei   = d_in[1];
    const float* Wl1  = (const float*)d_in[2];
    const float* bl1  = (const float*)d_in[3];
    const float* Wr1  = (const float*)d_in[4];
    const float* br1  = (const float*)d_in[5];
    const float* att1 = (const float*)d_in[6];
    const float* b1   = (const float*)d_in[7];
    const float* Wl2  = (const float*)d_in[8];
    const float* bl2  = (const float*)d_in[9];
    const float* Wr2  = (const float*)d_in[10];
    const float* br2  = (const float*)d_in[11];
    const float* att2 = (const float*)d_in[12];
    const float* b2   = (const float*)d_in[13];
    const float* gamma = (const float*)d_in[14];
    const float* beta  = (const float*)d_in[15];
    const float* Wc   = (const float*)d_in[16];
    const float* bc   = (const float*)d_in[17];
    float* out = (float*)d_out;

    float *xl, *xr, *h;
    cudaGetSymbolAddress((void**)&xl, g_xl);
    cudaGetSymbolAddress((void**)&xr, g_xr);
    cudaGetSymbolAddress((void**)&h,  g_h);

    detect_dtype<<<1, 32>>>((const unsigned int*)ei);
    convert_edges<<<(EE + 255) / 256, 256>>>(ei);

    // CSR build (dst identical for both layers)
    zero_cnt<<<(NN + 255) / 256, 256>>>();
    hist_dst<<<(EE + 255) / 256, 256>>>();
    scan_off<<<1, 1024>>>();
    scatter_csr<<<(EE + 255) / 256, 256>>>();

    dim3 ggrid1((NN + 127) / 128, (HCV + 127) / 128);
    const int nodeBlocks = (NN + 7) / 8;   // 8 warps / 256-thread block

    // ---- layer 1 ----
    gemm_bias<<<ggrid1, 256>>>(x, Wl1, bl1, xl, NN, FIN);
    gemm_bias<<<ggrid1, 256>>>(x, Wr1, br1, xr, NN, FIN);
    gat_node<<<nodeBlocks, 256>>>(att1, b1);
    zero_stats<<<1, 640>>>();
    bn_stats<<<512, 320>>>();
    bn_apply<<<1024, 320>>>(gamma, beta);

    // ---- layer 2 ----
    gemm_bias<<<ggrid1, 256>>>(h, Wl2, bl2, xl, NN, HCV);
    gemm_bias<<<ggrid1, 256>>>(h, Wr2, br2, xr, NN, HCV);
    gat_node<<<nodeBlocks, 256>>>(att2, b2);
    zero_stats<<<1, 640>>>();
    bn_stats<<<512, 320>>>();
    bn_apply<<<1024, 320>>>(gamma, beta);

    classifier<<<(NN * 32 + 255) / 256, 256>>>(Wc, bc, out);
}

// round 4
// speedup vs baseline: 2.2769x; 1.4179x over previous
#include <cuda_runtime.h>

#define NN 50000
#define EE 800000
#define FIN 128
#define HH 4
#define CC 73
#define HCV 292
#define BN_EPS 1e-5f

// ---------------- scratch (static device globals) ----------------
__device__ float g_xl[(size_t)NN * HCV];
__device__ float g_xr[(size_t)NN * HCV];
__device__ float g_h [(size_t)NN * HCV];
__device__ float g_stats[2 * HCV];
__device__ float g_bnsc[HCV];
__device__ float g_bnbt[HCV];
__device__ int   g_src[EE];
__device__ int   g_cnt[NN];
__device__ int   g_off[NN];
__device__ int   g_fill[NN];
__device__ int   g_csrc[EE];                // CSR: src node per slot
__device__ int   g_is64;

// ---------------- edge index dtype detect ----------------
__global__ void detect_dtype(const unsigned int* ei) {
    unsigned acc = 0;
    for (int i = threadIdx.x; i < 2048; i += 32) acc |= ei[2 * i + 1];
    #pragma unroll
    for (int o = 16; o; o >>= 1) acc |= __shfl_xor_sync(0xffffffffu, acc, o);
    if (threadIdx.x == 0) g_is64 = (acc == 0u) ? 1 : 0;
}

__global__ void zero_cnt() {
    int i = blockIdx.x * blockDim.x + threadIdx.x;
    if (i < NN) { g_cnt[i] = 0; g_fill[i] = 0; }
}

// convert + dst histogram fused. g_src holds src, dst only needed for CSR build.
__global__ void convert_hist(const void* ei) {
    int i = blockIdx.x * blockDim.x + threadIdx.x;
    if (i >= EE) return;
    int s, d;
    if (g_is64) {
        const long long* p = (const long long*)ei;
        s = (int)p[i]; d = (int)p[EE + i];
    } else {
        const int* p = (const int*)ei;
        s = p[i]; d = p[EE + i];
    }
    g_src[i] = s;
    atomicAdd(&g_cnt[d], 1);
}

__global__ void scan_off() {     // 1 block, 1024 threads
    __shared__ int part[1024];
    int t = threadIdx.x;
    const int PER = (NN + 1023) / 1024;
    int base = t * PER;
    int sum = 0;
    for (int i = 0; i < PER; i++) { int j = base + i; if (j < NN) sum += g_cnt[j]; }
    part[t] = sum;
    __syncthreads();
    for (int o = 1; o < 1024; o <<= 1) {
        int v = 0;
        if (t >= o) v = part[t - o];
        __syncthreads();
        if (t >= o) part[t] += v;
        __syncthreads();
    }
    int run = (t == 0) ? 0 : part[t - 1];
    for (int i = 0; i < PER; i++) {
        int j = base + i;
        if (j < NN) { g_off[j] = run; run += g_cnt[j]; }
    }
}

__global__ void scatter_csr(const void* ei) {
    int e = blockIdx.x * blockDim.x + threadIdx.x;
    if (e >= EE) return;
    int d;
    if (g_is64) d = (int)((const long long*)ei)[EE + e];
    else        d = ((const int*)ei)[EE + e];
    int p = g_off[d] + atomicAdd(&g_fill[d], 1);
    g_csrc[p] = g_src[e];
}

// ---------------- stacked GEMM: [Cl|Cr] = A @ [Wl|Wr]^T + [bl|br] ----------------
// A:[nrows,K], Wl/Wr:[HCV,K]; logical N = 2*HCV = 584, grid.y covers it.
__global__ void gemm2(const float* __restrict__ A,
                      const float* __restrict__ Wl, const float* __restrict__ Wr,
                      const float* __restrict__ bl, const float* __restrict__ br,
                      float* __restrict__ Cl, float* __restrict__ Cr,
                      int nrows, int K) {
    const int BM = 128, BN = 128, BK = 16, NTOT = 2 * HCV;
    __shared__ __align__(16) float As[BK][BM + 4];
    __shared__ __align__(16) float Ws[BK][BN + 4];
    int tid = threadIdx.x;               // 256 threads
    int tx = tid & 15, ty = tid >> 4;    // 16 x 16, each does 8x8
    int row0 = blockIdx.x * BM, col0 = blockIdx.y * BN;
    float acc[8][8];
    #pragma unroll
    for (int i = 0; i < 8; i++)
        #pragma unroll
        for (int j = 0; j < 8; j++) acc[i][j] = 0.f;

    for (int k0 = 0; k0 < K; k0 += BK) {
        #pragma unroll
        for (int i = tid; i < BM * BK; i += 256) {
            int r = i >> 4, c = i & 15;
            int gr = row0 + r, gc = k0 + c;
            As[c][r] = (gr < nrows && gc < K) ? A[(size_t)gr * K + gc] : 0.f;
        }
        #pragma unroll
        for (int i = tid; i < BN * BK; i += 256) {
            int r = i >> 4, c = i & 15;
            int gr = col0 + r, gc = k0 + c;
            float v = 0.f;
            if (gr < NTOT && gc < K) {
                const float* Wp = (gr < HCV) ? (Wl + (size_t)gr * K)
                                             : (Wr + (size_t)(gr - HCV) * K);
                v = Wp[gc];
            }
            Ws[c][r] = v;
        }
        __syncthreads();
        #pragma unroll
        for (int kk = 0; kk < BK; kk++) {
            float4 a0 = *reinterpret_cast<const float4*>(&As[kk][ty * 8]);
            float4 a1 = *reinterpret_cast<const float4*>(&As[kk][ty * 8 + 4]);
            float4 b0 = *reinterpret_cast<const float4*>(&Ws[kk][tx * 8]);
            float4 b1 = *reinterpret_cast<const float4*>(&Ws[kk][tx * 8 + 4]);
            float a[8] = {a0.x, a0.y, a0.z, a0.w, a1.x, a1.y, a1.z, a1.w};
            float b[8] = {b0.x, b0.y, b0.z, b0.w, b1.x, b1.y, b1.z, b1.w};
            #pragma unroll
            for (int i = 0; i < 8; i++)
                #pragma unroll
                for (int j = 0; j < 8; j++) acc[i][j] += a[i] * b[j];
        }
        __syncthreads();
    }
    #pragma unroll
    for (int i = 0; i < 8; i++) {
        int gr = row0 + ty * 8 + i;
        if (gr >= nrows) continue;
        #pragma unroll
        for (int j = 0; j < 8; j++) {
            int gc = col0 + tx * 8 + j;
            if (gc < HCV)       Cl[(size_t)gr * HCV + gc]         = acc[i][j] + __ldg(&bl[gc]);
            else if (gc < NTOT) Cr[(size_t)gr * HCV + (gc - HCV)] = acc[i][j] + __ldg(&br[gc - HCV]);
        }
    }
}

// ---------------- fused GATv2 node kernel (online softmax): warp per node ----------------
__global__ void gat_node(const float* __restrict__ att, const float* __restrict__ b) {
    int warp = (blockIdx.x * blockDim.x + threadIdx.x) >> 5;
    int lane = threadIdx.x & 31;
    if (warp >= NN) return;
    int n = warp;

    float xrr[10], attv[10], out[10];
    int hd[10];
    #pragma unroll
    for (int k = 0; k < 10; k++) {
        int c = lane + 32 * k;
        bool ok = c < HCV;
        xrr[k]  = ok ? g_xr[(size_t)n * HCV + c] : 0.f;
        attv[k] = ok ? __ldg(&att[c]) : 0.f;
        hd[k]   = ok ? (c / CC) : 0;
        out[k]  = 0.f;
    }
    int beg = g_off[n], cnt = g_cnt[n];

    float m0 = -1e30f, m1 = -1e30f, m2 = -1e30f, m3 = -1e30f;
    float d0 = 0.f, d1 = 0.f, d2 = 0.f, d3 = 0.f;

    for (int i = 0; i < cnt; i++) {
        const float* xl = g_xl + (size_t)g_csrc[beg + i] * HCV;
        float xlv[10];
        float a0 = 0.f, a1 = 0.f, a2 = 0.f, a3 = 0.f;
        #pragma unroll
        for (int k = 0; k < 10; k++) {
            int c = lane + 32 * k;
            float v = (c < HCV) ? xl[c] : 0.f;
            xlv[k] = v;
            float f = v + xrr[k];
            f = (f >= 0.f) ? f : 0.2f * f;
            float p = f * attv[k];
            if      (hd[k] == 0) a0 += p;
            else if (hd[k] == 1) a1 += p;
            else if (hd[k] == 2) a2 += p;
            else                 a3 += p;
        }
        #pragma unroll
        for (int o = 16; o; o >>= 1) {
            a0 += __shfl_xor_sync(0xffffffffu, a0, o);
            a1 += __shfl_xor_sync(0xffffffffu, a1, o);
            a2 += __shfl_xor_sync(0xffffffffu, a2, o);
            a3 += __shfl_xor_sync(0xffffffffu, a3, o);
        }
        // online softmax update (per head)
        float n0 = fmaxf(m0, a0), n1 = fmaxf(m1, a1);
        float n2 = fmaxf(m2, a2), n3 = fmaxf(m3, a3);
        float s0 = __expf(m0 - n0), s1 = __expf(m1 - n1);
        float s2 = __expf(m2 - n2), s3 = __expf(m3 - n3);
        float e0 = __expf(a0 - n0), e1 = __expf(a1 - n1);
        float e2 = __expf(a2 - n2), e3 = __expf(a3 - n3);
        d0 = d0 * s0 + e0; d1 = d1 * s1 + e1;
        d2 = d2 * s2 + e2; d3 = d3 * s3 + e3;
        m0 = n0; m1 = n1; m2 = n2; m3 = n3;
        #pragma unroll
        for (int k = 0; k < 10; k++) {
            float sh = (hd[k] == 0) ? s0 : (hd[k] == 1) ? s1 : (hd[k] == 2) ? s2 : s3;
            float eh = (hd[k] == 0) ? e0 : (hd[k] == 1) ? e1 : (hd[k] == 2) ? e2 : e3;
            out[k] = out[k] * sh + eh * xlv[k];
        }
    }
    float i0 = 1.f / (d0 + 1e-16f), i1 = 1.f / (d1 + 1e-16f);
    float i2 = 1.f / (d2 + 1e-16f), i3 = 1.f / (d3 + 1e-16f);
    #pragma unroll
    for (int k = 0; k < 10; k++) {
        int c = lane + 32 * k;
        if (c < HCV) {
            float ih = (hd[k] == 0) ? i0 : (hd[k] == 1) ? i1 : (hd[k] == 2) ? i2 : i3;
            g_h[(size_t)n * HCV + c] = out[k] * ih + __ldg(&b[c]);
        }
    }
}

// ---------------- batchnorm ----------------
__global__ void zero_stats() {
    int t = threadIdx.x;
    if (t < 2 * HCV) g_stats[t] = 0.f;
}
__global__ void bn_stats() {
    int t = threadIdx.x;
    if (t >= HCV) return;
    float s = 0.f, sq = 0.f;
    for (int n = blockIdx.x; n < NN; n += gridDim.x) {
        float v = g_h[(size_t)n * HCV + t];
        s += v; sq += v * v;
    }
    atomicAdd(&g_stats[t], s);
    atomicAdd(&g_stats[HCV + t], sq);
}
__global__ void bn_prep(const float* __restrict__ gamma, const float* __restrict__ beta) {
    int t = threadIdx.x;
    if (t >= HCV) return;
    float mu = g_stats[t] * (1.f / NN);
    float var = g_stats[HCV + t] * (1.f / NN) - mu * mu;
    float sc = rsqrtf(var + BN_EPS) * gamma[t];
    g_bnsc[t] = sc;
    g_bnbt[t] = beta[t] - mu * sc;
}
__global__ void bn_apply() {
    int t = threadIdx.x;
    if (t >= HCV) return;
    float sc = g_bnsc[t], bt = g_bnbt[t];
    for (int n = blockIdx.x; n < NN; n += gridDim.x) {
        size_t idx = (size_t)n * HCV + t;
        float y = g_h[idx] * sc + bt;
        g_h[idx] = (y >= 0.f) ? y : 0.01f * y;
    }
}

// ---------------- fused layer-2 BN + leaky + classifier ----------------
__global__ void bn_classify(const float* __restrict__ Wc, const float* __restrict__ bc,
                            float* __restrict__ out) {
    int w = (blockIdx.x * blockDim.x + threadIdx.x) >> 5;
    int lane = threadIdx.x & 31;
    if (w >= NN) return;
    const float* hrow = g_h + (size_t)w * HCV;
    float c0 = 0.f, c1 = 0.f;
    #pragma unroll
    for (int k = 0; k < 10; k++) {
        int j = lane + 32 * k;
        if (j < HCV) {
            float y = hrow[j] * __ldg(&g_bnsc[j]) + __ldg(&g_bnbt[j]);
            y = (y >= 0.f) ? y : 0.01f * y;
            c0 += y * __ldg(&Wc[j]);
            c1 += y * __ldg(&Wc[HCV + j]);
        }
    }
    #pragma unroll
    for (int o = 16; o; o >>= 1) {
        c0 += __shfl_xor_sync(0xffffffffu, c0, o);
        c1 += __shfl_xor_sync(0xffffffffu, c1, o);
    }
    if (lane == 0) {
        out[2 * w]     = c0 + bc[0];
        out[2 * w + 1] = c1 + bc[1];
    }
}

// ---------------- host orchestration ----------------
extern "C" void kernel_launch(void* const* d_in, const int* in_sizes, int n_in,
                              void* d_out, int out_size) {
    const float* x    = (const float*)d_in[0];
    const void*  ei   = d_in[1];
    const float* Wl1  = (const float*)d_in[2];
    const float* bl1  = (const float*)d_in[3];
    const float* Wr1  = (const float*)d_in[4];
    const float* br1  = (const float*)d_in[5];
    const float* att1 = (const float*)d_in[6];
    const float* b1   = (const float*)d_in[7];
    const float* Wl2  = (const float*)d_in[8];
    const float* bl2  = (const float*)d_in[9];
    const float* Wr2  = (const float*)d_in[10];
    const float* br2  = (const float*)d_in[11];
    const float* att2 = (const float*)d_in[12];
    const float* b2   = (const float*)d_in[13];
    const float* gamma = (const float*)d_in[14];
    const float* beta  = (const float*)d_in[15];
    const float* Wc   = (const float*)d_in[16];
    const float* bc   = (const float*)d_in[17];
    float* out = (float*)d_out;

    float *xl, *xr, *h;
    cudaGetSymbolAddress((void**)&xl, g_xl);
    cudaGetSymbolAddress((void**)&xr, g_xr);
    cudaGetSymbolAddress((void**)&h,  g_h);

    detect_dtype<<<1, 32>>>((const unsigned int*)ei);
    zero_cnt<<<(NN + 255) / 256, 256>>>();
    convert_hist<<<(EE + 255) / 256, 256>>>(ei);
    scan_off<<<1, 1024>>>();
    scatter_csr<<<(EE + 255) / 256, 256>>>(ei);

    dim3 ggrid((NN + 127) / 128, (2 * HCV + 127) / 128);   // (391, 5)
    const int nodeBlocks = (NN + 7) / 8;                   // 8 warps / block

    // ---- layer 1 ----
    gemm2<<<ggrid, 256>>>(x, Wl1, Wr1, bl1, br1, xl, xr, NN, FIN);
    gat_node<<<nodeBlocks, 256>>>(att1, b1);
    zero_stats<<<1, 640>>>();
    bn_stats<<<512, 320>>>();
    bn_prep<<<1, 320>>>(gamma, beta);
    bn_apply<<<1024, 320>>>();

    // ---- layer 2 ----
    gemm2<<<ggrid, 256>>>(h, Wl2, Wr2, bl2, br2, xl, xr, NN, HCV);
    gat_node<<<nodeBlocks, 256>>>(att2, b2);
    zero_stats<<<1, 640>>>();
    bn_stats<<<512, 320>>>();
    bn_prep<<<1, 320>>>(gamma, beta);
    bn_classify<<<(NN * 32 + 255) / 256, 256>>>(Wc, bc, out);
}

// round 5
// speedup vs baseline: 3.9001x; 1.7129x over previous
#include <cuda_runtime.h>
#include <cstdint>

#define NN 50000
#define EE 800000
#define FIN 128
#define HH 4
#define CC 73
#define HCV 292
#define BN_EPS 1e-5f

// ---------------- scratch (static device globals) ----------------
__device__ float g_xl[(size_t)NN * HCV];
__device__ float g_xr[(size_t)NN * HCV];
__device__ float g_h [(size_t)NN * HCV];
__device__ float g_stats[2 * HCV];
__device__ float g_bnsc[HCV];
__device__ float g_bnbt[HCV];
__device__ int   g_src[EE];
__device__ int   g_cnt[NN];
__device__ int   g_off[NN];
__device__ int   g_fill[NN];
__device__ int   g_csrc[EE];
__device__ int   g_is64;

#define SCAN_BLKS 196                       // ceil(50000/256)
__device__ int   g_bsum[SCAN_BLKS];
__device__ int   g_boff[SCAN_BLKS];

// ---------------- edge index dtype detect ----------------
__global__ void detect_dtype(const unsigned int* ei) {
    unsigned acc = 0;
    for (int i = threadIdx.x; i < 2048; i += 32) acc |= ei[2 * i + 1];
    #pragma unroll
    for (int o = 16; o; o >>= 1) acc |= __shfl_xor_sync(0xffffffffu, acc, o);
    if (threadIdx.x == 0) g_is64 = (acc == 0u) ? 1 : 0;
}

__global__ void zero_cnt() {
    int i = blockIdx.x * blockDim.x + threadIdx.x;
    if (i < NN) { g_cnt[i] = 0; g_fill[i] = 0; }
}

__global__ void convert_hist(const void* ei) {
    int i = blockIdx.x * blockDim.x + threadIdx.x;
    if (i >= EE) return;
    int s, d;
    if (g_is64) {
        const long long* p = (const long long*)ei;
        s = (int)p[i]; d = (int)p[EE + i];
    } else {
        const int* p = (const int*)ei;
        s = p[i]; d = p[EE + i];
    }
    g_src[i] = s;
    atomicAdd(&g_cnt[d], 1);
}

// ---------------- hierarchical exclusive scan of g_cnt -> g_off ----------------
__global__ void scan_blocksum() {
    __shared__ int sh[256];
    int i = blockIdx.x * 256 + threadIdx.x;
    int v = (i < NN) ? g_cnt[i] : 0;
    sh[threadIdx.x] = v;
    __syncthreads();
    for (int o = 128; o; o >>= 1) {
        if (threadIdx.x < o) sh[threadIdx.x] += sh[threadIdx.x + o];
        __syncthreads();
    }
    if (threadIdx.x == 0) g_bsum[blockIdx.x] = sh[0];
}
__global__ void scan_top() {      // 1 block, 256 threads over SCAN_BLKS sums
    __shared__ int sh[256];
    int t = threadIdx.x;
    sh[t] = (t < SCAN_BLKS) ? g_bsum[t] : 0;
    __syncthreads();
    for (int o = 1; o < 256; o <<= 1) {
        int v = (t >= o) ? sh[t - o] : 0;
        __syncthreads();
        sh[t] += v;
        __syncthreads();
    }
    if (t < SCAN_BLKS) g_boff[t] = (t == 0) ? 0 : sh[t - 1];
}
__global__ void scan_local() {
    __shared__ int sh[256];
    int t = threadIdx.x;
    int i = blockIdx.x * 256 + t;
    int v = (i < NN) ? g_cnt[i] : 0;
    sh[t] = v;
    __syncthreads();
    for (int o = 1; o < 256; o <<= 1) {
        int u = (t >= o) ? sh[t - o] : 0;
        __syncthreads();
        sh[t] += u;
        __syncthreads();
    }
    if (i < NN) g_off[i] = g_boff[blockIdx.x] + sh[t] - v;   // exclusive
}

__global__ void scatter_csr(const void* ei) {
    int e = blockIdx.x * blockDim.x + threadIdx.x;
    if (e >= EE) return;
    int d;
    if (g_is64) d = (int)((const long long*)ei)[EE + e];
    else        d = ((const int*)ei)[EE + e];
    int p = g_off[d] + atomicAdd(&g_fill[d], 1);
    g_csrc[p] = g_src[e];
}

// ---------------- TF32 tensor-core stacked GEMM ----------------
// [Cl|Cr] = A @ [Wl|Wr]^T + [bl|br];  A:[nrows,K], Wl/Wr:[HCV,K] row-major.
// BM=128 BN=64 BK=32; 256 thr = 8 warps (4x2), warp tile 32x32, mma m16n8k8.
#define PAD 36

__device__ __forceinline__ uint32_t f2tf32(float f) {
    uint32_t r;
    asm("cvt.rna.tf32.f32 %0, %1;" : "=r"(r) : "f"(f));
    return r;
}

__global__ __launch_bounds__(256, 2)
void gemm2_tc(const float* __restrict__ A,
              const float* __restrict__ Wl, const float* __restrict__ Wr,
              const float* __restrict__ bl, const float* __restrict__ br,
              float* __restrict__ Cl, float* __restrict__ Cr,
              int nrows, int K) {
    const int BM = 128, BN = 64, BK = 32, NTOT = 2 * HCV;
    __shared__ uint32_t As[BM * PAD];
    __shared__ uint32_t Bs[BN * PAD];

    int tid  = threadIdx.x;
    int wid  = tid >> 5, lane = tid & 31;
    int wm   = wid & 3, wn = wid >> 2;          // 4 x 2 warps
    int g    = lane >> 2, tig = lane & 3;       // mma group / thread-in-group
    int row0 = blockIdx.x * BM, col0 = blockIdx.y * BN;

    // A: 128x32 = 1024 float4; thread t: row=t/2, 2 float4 at cols (t%2)*16 + {0,8}? -> 4 f4 each
    int arow = tid >> 1;                        // 0..127
    int acol4 = (tid & 1) * 4;                  // 0 or 4 (float4 idx); +0..3? we do 4 f4: cols (t&1)*16 + j*4
    int brow = tid >> 2;                        // 0..63
    int bcol4 = (tid & 3) * 2;                  // 2 float4 each: cols (t&3)*8 + {0,4}

    float acc[2][4][4];
    #pragma unroll
    for (int m = 0; m < 2; m++)
        #pragma unroll
        for (int n = 0; n < 4; n++)
            #pragma unroll
            for (int c = 0; c < 4; c++) acc[m][n][c] = 0.f;

    int nChunks = (K + BK - 1) / BK;

    float4 pa[4], pb[2];

    // -------- prefetch chunk 0 --------
    {
        int k0 = 0;
        const float* Arow = A + (size_t)(row0 + arow) * K;
        bool rok = (row0 + arow) < nrows;
        #pragma unroll
        for (int j = 0; j < 4; j++) {
            int c = (tid & 1) * 16 + j * 4;
            bool ok = rok && (k0 + c + 4 <= K);
            pa[j] = ok ? *reinterpret_cast<const float4*>(Arow + k0 + c)
                       : make_float4(0.f, 0.f, 0.f, 0.f);
        }
        int gn = col0 + brow;
        const float* Wrow = (gn < HCV) ? (Wl + (size_t)gn * K)
                         : (gn < NTOT) ? (Wr + (size_t)(gn - HCV) * K) : nullptr;
        #pragma unroll
        for (int j = 0; j < 2; j++) {
            int c = (tid & 3) * 8 + j * 4;
            bool ok = Wrow && (k0 + c + 4 <= K);
            pb[j] = ok ? *reinterpret_cast<const float4*>(Wrow + k0 + c)
                       : make_float4(0.f, 0.f, 0.f, 0.f);
        }
    }

    for (int ch = 0; ch < nChunks; ch++) {
        // -------- store prefetched regs to smem (with tf32 cvt) --------
        #pragma unroll
        for (int j = 0; j < 4; j++) {
            int c = (tid & 1) * 16 + j * 4;
            uint32_t* d = &As[arow * PAD + c];
            d[0] = f2tf32(pa[j].x); d[1] = f2tf32(pa[j].y);
            d[2] = f2tf32(pa[j].z); d[3] = f2tf32(pa[j].w);
        }
        #pragma unroll
        for (int j = 0; j < 2; j++) {
            int c = (tid & 3) * 8 + j * 4;
            uint32_t* d = &Bs[brow * PAD + c];
            d[0] = f2tf32(pb[j].x); d[1] = f2tf32(pb[j].y);
            d[2] = f2tf32(pb[j].z); d[3] = f2tf32(pb[j].w);
        }
        __syncthreads();

        // -------- prefetch next chunk --------
        if (ch + 1 < nChunks) {
            int k0 = (ch + 1) * BK;
            const float* Arow = A + (size_t)(row0 + arow) * K;
            bool rok = (row0 + arow) < nrows;
            #pragma unroll
            for (int j = 0; j < 4; j++) {
                int c = (tid & 1) * 16 + j * 4;
                bool ok = rok && (k0 + c + 4 <= K);
                pa[j] = ok ? *reinterpret_cast<const float4*>(Arow + k0 + c)
                           : make_float4(0.f, 0.f, 0.f, 0.f);
            }
            int gn = col0 + brow;
            const float* Wrow = (gn < HCV) ? (Wl + (size_t)gn * K)
                             : (gn < NTOT) ? (Wr + (size_t)(gn - HCV) * K) : nullptr;
            #pragma unroll
            for (int j = 0; j < 2; j++) {
                int c = (tid & 3) * 8 + j * 4;
                bool ok = Wrow && (k0 + c + 4 <= K);
                pb[j] = ok ? *reinterpret_cast<const float4*>(Wrow + k0 + c)
                           : make_float4(0.f, 0.f, 0.f, 0.f);
            }
        }

        // -------- compute: 4 k8-steps --------
        #pragma unroll
        for (int kk = 0; kk < 4; kk++) {
            int kb = kk * 8;
            uint32_t af[2][4], bf[4][2];
            #pragma unroll
            for (int m = 0; m < 2; m++) {
                int r = wm * 32 + m * 16 + g;
                af[m][0] = As[r * PAD + kb + tig];
                af[m][1] = As[(r + 8) * PAD + kb + tig];
                af[m][2] = As[r * PAD + kb + tig + 4];
                af[m][3] = As[(r + 8) * PAD + kb + tig + 4];
            }
            #pragma unroll
            for (int n = 0; n < 4; n++) {
                int r = wn * 32 + n * 8 + g;
                bf[n][0] = Bs[r * PAD + kb + tig];
                bf[n][1] = Bs[r * PAD + kb + tig + 4];
            }
            #pragma unroll
            for (int m = 0; m < 2; m++)
                #pragma unroll
                for (int n = 0; n < 4; n++) {
                    asm volatile(
                        "mma.sync.aligned.m16n8k8.row.col.f32.tf32.tf32.f32 "
                        "{%0,%1,%2,%3}, {%4,%5,%6,%7}, {%8,%9}, {%0,%1,%2,%3};\n"
                        : "+f"(acc[m][n][0]), "+f"(acc[m][n][1]),
                          "+f"(acc[m][n][2]), "+f"(acc[m][n][3])
                        : "r"(af[m][0]), "r"(af[m][1]), "r"(af[m][2]), "r"(af[m][3]),
                          "r"(bf[n][0]), "r"(bf[n][1]));
                }
        }
        __syncthreads();
    }

    // -------- epilogue: bias + split store --------
    #pragma unroll
    for (int m = 0; m < 2; m++) {
        int gr0 = row0 + wm * 32 + m * 16 + g;
        int gr1 = gr0 + 8;
        #pragma unroll
        for (int n = 0; n < 4; n++) {
            int gc = col0 + wn * 32 + n * 8 + 2 * tig;   // even, pair never straddles 292
            float bia0, bia1;
            float *base;
            int cc;
            if (gc < HCV) {
                bia0 = __ldg(&bl[gc]); bia1 = __ldg(&bl[gc + 1]);
                base = Cl; cc = gc;
            } else if (gc < NTOT) {
                cc = gc - HCV;
                bia0 = __ldg(&br[cc]); bia1 = __ldg(&br[cc + 1]);
                base = Cr;
            } else continue;
            if (gr0 < nrows) {
                base[(size_t)gr0 * HCV + cc]     = acc[m][n][0] + bia0;
                base[(size_t)gr0 * HCV + cc + 1] = acc[m][n][1] + bia1;
            }
            if (gr1 < nrows) {
                base[(size_t)gr1 * HCV + cc]     = acc[m][n][2] + bia0;
                base[(size_t)gr1 * HCV + cc + 1] = acc[m][n][3] + bia1;
            }
        }
    }
}

// ---------------- fused GATv2 node kernel (online softmax): warp per node ----------------
__global__ void gat_node(const float* __restrict__ att, const float* __restrict__ b) {
    int warp = (blockIdx.x * blockDim.x + threadIdx.x) >> 5;
    int lane = threadIdx.x & 31;
    if (warp >= NN) return;
    int n = warp;

    float xrr[10], attv[10], out[10];
    int hd[10];
    #pragma unroll
    for (int k = 0; k < 10; k++) {
        int c = lane + 32 * k;
        bool ok = c < HCV;
        xrr[k]  = ok ? g_xr[(size_t)n * HCV + c] : 0.f;
        attv[k] = ok ? __ldg(&att[c]) : 0.f;
        hd[k]   = ok ? (c / CC) : 0;
        out[k]  = 0.f;
    }
    int beg = g_off[n], cnt = g_cnt[n];

    float m0 = -1e30f, m1 = -1e30f, m2 = -1e30f, m3 = -1e30f;
    float d0 = 0.f, d1 = 0.f, d2 = 0.f, d3 = 0.f;

    for (int i = 0; i < cnt; i++) {
        const float* xl = g_xl + (size_t)g_csrc[beg + i] * HCV;
        float xlv[10];
        float a0 = 0.f, a1 = 0.f, a2 = 0.f, a3 = 0.f;
        #pragma unroll
        for (int k = 0; k < 10; k++) {
            int c = lane + 32 * k;
            float v = (c < HCV) ? xl[c] : 0.f;
            xlv[k] = v;
            float f = v + xrr[k];
            f = (f >= 0.f) ? f : 0.2f * f;
            float p = f * attv[k];
            if      (hd[k] == 0) a0 += p;
            else if (hd[k] == 1) a1 += p;
            else if (hd[k] == 2) a2 += p;
            else                 a3 += p;
        }
        #pragma unroll
        for (int o = 16; o; o >>= 1) {
            a0 += __shfl_xor_sync(0xffffffffu, a0, o);
            a1 += __shfl_xor_sync(0xffffffffu, a1, o);
            a2 += __shfl_xor_sync(0xffffffffu, a2, o);
            a3 += __shfl_xor_sync(0xffffffffu, a3, o);
        }
        float n0 = fmaxf(m0, a0), n1 = fmaxf(m1, a1);
        float n2 = fmaxf(m2, a2), n3 = fmaxf(m3, a3);
        float s0 = __expf(m0 - n0), s1 = __expf(m1 - n1);
        float s2 = __expf(m2 - n2), s3 = __expf(m3 - n3);
        float e0 = __expf(a0 - n0), e1 = __expf(a1 - n1);
        float e2 = __expf(a2 - n2), e3 = __expf(a3 - n3);
        d0 = d0 * s0 + e0; d1 = d1 * s1 + e1;
        d2 = d2 * s2 + e2; d3 = d3 * s3 + e3;
        m0 = n0; m1 = n1; m2 = n2; m3 = n3;
        #pragma unroll
        for (int k = 0; k < 10; k++) {
            float sh = (hd[k] == 0) ? s0 : (hd[k] == 1) ? s1 : (hd[k] == 2) ? s2 : s3;
            float eh = (hd[k] == 0) ? e0 : (hd[k] == 1) ? e1 : (hd[k] == 2) ? e2 : e3;
            out[k] = out[k] * sh + eh * xlv[k];
        }
    }
    float i0 = 1.f / (d0 + 1e-16f), i1 = 1.f / (d1 + 1e-16f);
    float i2 = 1.f / (d2 + 1e-16f), i3 = 1.f / (d3 + 1e-16f);
    #pragma unroll
    for (int k = 0; k < 10; k++) {
        int c = lane + 32 * k;
        if (c < HCV) {
            float ih = (hd[k] == 0) ? i0 : (hd[k] == 1) ? i1 : (hd[k] == 2) ? i2 : i3;
            g_h[(size_t)n * HCV + c] = out[k] * ih + __ldg(&b[c]);
        }
    }
}

// ---------------- batchnorm ----------------
__global__ void zero_stats() {
    int t = threadIdx.x;
    if (t < 2 * HCV) g_stats[t] = 0.f;
}
__global__ void bn_stats() {
    int t = threadIdx.x;
    if (t >= HCV) return;
    float s = 0.f, sq = 0.f;
    for (int n = blockIdx.x; n < NN; n += gridDim.x) {
        float v = g_h[(size_t)n * HCV + t];
        s += v; sq += v * v;
    }
    atomicAdd(&g_stats[t], s);
    atomicAdd(&g_stats[HCV + t], sq);
}
__global__ void bn_prep(const float* __restrict__ gamma, const float* __restrict__ beta) {
    int t = threadIdx.x;
    if (t >= HCV) return;
    float mu = g_stats[t] * (1.f / NN);
    float var = g_stats[HCV + t] * (1.f / NN) - mu * mu;
    float sc = rsqrtf(var + BN_EPS) * gamma[t];
    g_bnsc[t] = sc;
    g_bnbt[t] = beta[t] - mu * sc;
}
__global__ void bn_apply() {
    int t = threadIdx.x;
    if (t >= HCV) return;
    float sc = g_bnsc[t], bt = g_bnbt[t];
    for (int n = blockIdx.x; n < NN; n += gridDim.x) {
        size_t idx = (size_t)n * HCV + t;
        float y = g_h[idx] * sc + bt;
        g_h[idx] = (y >= 0.f) ? y : 0.01f * y;
    }
}

// ---------------- fused layer-2 BN + leaky + classifier ----------------
__global__ void bn_classify(const float* __restrict__ Wc, const float* __restrict__ bc,
                            float* __restrict__ out) {
    int w = (blockIdx.x * blockDim.x + threadIdx.x) >> 5;
    int lane = threadIdx.x & 31;
    if (w >= NN) return;
    const float* hrow = g_h + (size_t)w * HCV;
    float c0 = 0.f, c1 = 0.f;
    #pragma unroll
    for (int k = 0; k < 10; k++) {
        int j = lane + 32 * k;
        if (j < HCV) {
            float y = hrow[j] * __ldg(&g_bnsc[j]) + __ldg(&g_bnbt[j]);
            y = (y >= 0.f) ? y : 0.01f * y;
            c0 += y * __ldg(&Wc[j]);
            c1 += y * __ldg(&Wc[HCV + j]);
        }
    }
    #pragma unroll
    for (int o = 16; o; o >>= 1) {
        c0 += __shfl_xor_sync(0xffffffffu, c0, o);
        c1 += __shfl_xor_sync(0xffffffffu, c1, o);
    }
    if (lane == 0) {
        out[2 * w]     = c0 + bc[0];
        out[2 * w + 1] = c1 + bc[1];
    }
}

// ---------------- host orchestration ----------------
extern "C" void kernel_launch(void* const* d_in, const int* in_sizes, int n_in,
                              void* d_out, int out_size) {
    const float* x    = (const float*)d_in[0];
    const void*  ei   = d_in[1];
    const float* Wl1  = (const float*)d_in[2];
    const float* bl1  = (const float*)d_in[3];
    const float* Wr1  = (const float*)d_in[4];
    const float* br1  = (const float*)d_in[5];
    const float* att1 = (const float*)d_in[6];
    const float* b1   = (const float*)d_in[7];
    const float* Wl2  = (const float*)d_in[8];
    const float* bl2  = (const float*)d_in[9];
    const float* Wr2  = (const float*)d_in[10];
    const float* br2  = (const float*)d_in[11];
    const float* att2 = (const float*)d_in[12];
    const float* b2   = (const float*)d_in[13];
    const float* gamma = (const float*)d_in[14];
    const float* beta  = (const float*)d_in[15];
    const float* Wc   = (const float*)d_in[16];
    const float* bc   = (const float*)d_in[17];
    float* out = (float*)d_out;

    float *xl, *xr, *h;
    cudaGetSymbolAddress((void**)&xl, g_xl);
    cudaGetSymbolAddress((void**)&xr, g_xr);
    cudaGetSymbolAddress((void**)&h,  g_h);

    detect_dtype<<<1, 32>>>((const unsigned int*)ei);
    zero_cnt<<<(NN + 255) / 256, 256>>>();
    convert_hist<<<(EE + 255) / 256, 256>>>(ei);
    scan_blocksum<<<SCAN_BLKS, 256>>>();
    scan_top<<<1, 256>>>();
    scan_local<<<SCAN_BLKS, 256>>>();
    scatter_csr<<<(EE + 255) / 256, 256>>>(ei);

    dim3 ggrid((NN + 127) / 128, (2 * HCV + 63) / 64);     // (391, 10)
    const int nodeBlocks = (NN + 7) / 8;

    // ---- layer 1 ----
    gemm2_tc<<<ggrid, 256>>>(x, Wl1, Wr1, bl1, br1, xl, xr, NN, FIN);
    gat_node<<<nodeBlocks, 256>>>(att1, b1);
    zero_stats<<<1, 640>>>();
    bn_stats<<<512, 320>>>();
    bn_prep<<<1, 320>>>(gamma, beta);
    bn_apply<<<1024, 320>>>();

    // ---- layer 2 ----
    gemm2_tc<<<ggrid, 256>>>(h, Wl2, Wr2, bl2, br2, xl, xr, NN, HCV);
    gat_node<<<nodeBlocks, 256>>>(att2, b2);
    zero_stats<<<1, 640>>>();
    bn_stats<<<512, 320>>>();
    bn_prep<<<1, 320>>>(gamma, beta);
    bn_classify<<<(NN * 32 + 255) / 256, 256>>>(Wc, bc, out);
}